// round 14
// baseline (speedup 1.0000x reference)
#include <cuda_runtime.h>
#include <cuda_fp16.h>
#include <math.h>
#include <math_constants.h>
#include <stdint.h>

// Problem constants
#define NB   32
#define NT   4096
#define NQD  1024
#define NMD  512
#define NAD  128
#define NF   32
#define NKW  31
#define NPAD 15

// Score-kernel tiling
#define TILE_T  128
#define KCH     64          // K per chunk; loc chunk (chunk 8) uses cols 0..31
#define NCHUNK  8
#define ASTR    72          // padded row stride in elems (144 B, 16B-multiple)
#define TPB     (NT / TILE_T)          // 32 tiles per batch
#define NTILES  (NB * TPB)             // 1024 work items

// ---------------------------------------------------------------------------
// Device scratch (no allocation allowed).
// ---------------------------------------------------------------------------
__device__ alignas(16) float g_pq[NB * NAD];
__device__ alignas(16) float g_score[NB * NT];
__device__ unsigned g_ticket;
// fp16 B operands: [chunk][a(128)][k(64)] packed as uint4 (8 halfs)
__device__ uint4 g_B4[NCHUNK * TILE_T * KCH / 8];
__device__ uint4 g_Wl4[TILE_T * KCH / 8];   // cols 32..63 zero
// Split-softmax context partials
__device__ alignas(16) float g_pctx[NTILES * NMD];   // 2 MB
__device__ float g_pm[NTILES];
__device__ float g_pz[NTILES];

// ---------------------------------------------------------------------------
// Shared memory
// ---------------------------------------------------------------------------
struct ScoreSmem {
    alignas(16) unsigned short A[2][TILE_T * ASTR];
    alignas(16) unsigned short B[2][TILE_T * ASTR];
    float pqc[NAD];
    float vw[NAD];
    float al[2][TILE_T + NKW - 1];
    float ws[NF * 2 * NKW];     // 1984 floats
    float cb[NF];
    float part[2][TILE_T];
    float wexp[TILE_T];
    float redm[4];
    float redz[4];
    unsigned ticket;
};
static_assert(sizeof(ScoreSmem) <= 100 * 1024, "smem overflow");

// ---------------------------------------------------------------------------
// Helpers
// ---------------------------------------------------------------------------
__device__ __forceinline__ uint32_t smem_u32(const void* p) {
    uint32_t r;
    asm("{ .reg .u64 t; cvta.to.shared.u64 t, %1; cvt.u32.u64 %0, t; }"
        : "=r"(r) : "l"(p));
    return r;
}

__device__ __forceinline__ void ldsm4(uint32_t* r, uint32_t addr) {
    asm volatile("ldmatrix.sync.aligned.m8n8.x4.shared.b16 {%0,%1,%2,%3}, [%4];"
                 : "=r"(r[0]), "=r"(r[1]), "=r"(r[2]), "=r"(r[3]) : "r"(addr));
}

__device__ __forceinline__ void mma16816(float* c, const uint32_t* a,
                                         const uint32_t* b) {
    asm volatile(
        "mma.sync.aligned.m16n8k16.row.col.f32.f16.f16.f32 "
        "{%0,%1,%2,%3}, {%4,%5,%6,%7}, {%8,%9}, {%0,%1,%2,%3};"
        : "+f"(c[0]), "+f"(c[1]), "+f"(c[2]), "+f"(c[3])
        : "r"(a[0]), "r"(a[1]), "r"(a[2]), "r"(a[3]), "r"(b[0]), "r"(b[1]));
}

#define CP_ASYNC16(dst_u32, src_ptr) \
    asm volatile("cp.async.cg.shared.global [%0], [%1], 16;" \
                 :: "r"(dst_u32), "l"(src_ptr))
#define CP_COMMIT() asm volatile("cp.async.commit_group;")
#define CP_WAIT0()  asm volatile("cp.async.wait_group 0;")

__device__ __forceinline__ float tanh_fast(float x) {
    x = fminf(fmaxf(x, -20.f), 20.f);
    float e = __expf(-2.f * x);
    return __fdividef(1.f - e, 1.f + e);
}

// ---------------------------------------------------------------------------
// Prep: convert Wm / Wl to fp16, [chunk][a][k64] layout; Wl cols>=32 zeroed
// ---------------------------------------------------------------------------
__global__ void prep_kernel(const float* __restrict__ Wm,
                            const float* __restrict__ Wl) {
    int idx = blockIdx.x * blockDim.x + threadIdx.x;
    unsigned short* bp = (unsigned short*)g_B4;
    unsigned short* wp = (unsigned short*)g_Wl4;
    if (idx < NMD * NAD) {
        int k = idx >> 7, a = idx & 127;
        int c = k >> 6, kk = k & 63;
        __half h = __float2half_rn(Wm[k * NAD + a]);
        bp[c * (TILE_T * KCH) + a * KCH + kk] = ((__half_raw)h).x;
    } else if (idx < NMD * NAD + TILE_T * KCH) {
        int r = idx - NMD * NAD;
        int a = r >> 6, kk = r & 63;
        float v = (kk < NF) ? Wl[kk * NAD + a] : 0.0f;
        __half h = __float2half_rn(v);
        wp[a * KCH + kk] = ((__half_raw)h).x;
    }
}

// ---------------------------------------------------------------------------
// Kernel 1: processed query + ticket reset
// ---------------------------------------------------------------------------
__global__ void pq_kernel(const float* __restrict__ query,
                          const float* __restrict__ Wq,
                          const float* __restrict__ bq) {
    __shared__ float qs[NQD];
    __shared__ float partial[256];
    int b = blockIdx.x;
    int tid = threadIdx.x;
    if (b == 0 && tid == 0) g_ticket = 0;
    for (int i = tid; i < NQD; i += 256)
        qs[i] = query[b * NQD + i];
    __syncthreads();
    int a = tid & 127;
    int h = tid >> 7;
    float acc = 0.f;
    int q0 = h * (NQD / 2);
#pragma unroll 8
    for (int q = 0; q < NQD / 2; q++)
        acc = fmaf(qs[q0 + q], Wq[(q0 + q) * NAD + a], acc);
    partial[tid] = acc;
    __syncthreads();
    if (tid < 128)
        g_pq[b * NAD + a] = bq[a] + partial[tid] + partial[tid + 128];
}

// ---------------------------------------------------------------------------
// Kernel 2: PERSISTENT fused score kernel + split-softmax context partials.
// fp16 GEMM KCH=64; after the score epilogue each tile computes
// (m_i, Z_i, ctx_i = sum_t exp(s_t - m_i) * memory[t][:]) from L2-hot rows.
// ---------------------------------------------------------------------------
__global__ __launch_bounds__(256, 2)
void score_kernel(const float* __restrict__ memory,
                  const float* __restrict__ alignments,
                  const unsigned char* __restrict__ mask,
                  const float* __restrict__ bm,
                  const float* __restrict__ conv_w,
                  const float* __restrict__ conv_b,
                  const float* __restrict__ bl,
                  const float* __restrict__ v_w,
                  const float* __restrict__ v_b) {
    extern __shared__ char smem_raw[];
    ScoreSmem& S = *reinterpret_cast<ScoreSmem*>(smem_raw);

    const int tid  = threadIdx.x;
    const int lane = tid & 31;
    const int wid  = tid >> 5;
    const int wm   = wid >> 2;
    const int wn   = wid & 3;
    const int g    = lane >> 2;
    const int tg   = lane & 3;

    for (int i = tid; i < NF * 2 * NKW; i += 256) S.ws[i] = conv_w[i];
    if (tid < NF) S.cb[tid] = conv_b[tid];
    const float vb = *v_b;

    const uint32_t uA[2] = {smem_u32(S.A[0]), smem_u32(S.A[1])};
    const uint32_t uB[2] = {smem_u32(S.B[0]), smem_u32(S.B[1])};

    // ldmatrix per-lane addressing
    const int aRow  = wm * 64 + (lane & 15);
    const int aColX = (lane >> 4) * 8;
    const int bRow  = wn * 32 + ((lane >> 4) << 3) + (lane & 7);
    const int bColX = ((lane >> 3) & 1) * 8;

    float4 a4[2][2];
    const float* memb = memory;

    auto loadA_half = [&](int c, int h) {
#pragma unroll
        for (int u = 0; u < 2; u++) {
            int unit = tid + (2 * h + u) * 256;
            int t = unit >> 3, g8 = unit & 7;
            const float* src = memb + (size_t)t * NMD + c * KCH + g8 * 8;
            a4[u][0] = *(const float4*)src;
            a4[u][1] = *(const float4*)(src + 4);
        }
    };
    auto convertA_half = [&](int buf, int h) {
#pragma unroll
        for (int u = 0; u < 2; u++) {
            int unit = tid + (2 * h + u) * 256;
            int t = unit >> 3, g8 = unit & 7;
            __half2 h0 = __floats2half2_rn(a4[u][0].x, a4[u][0].y);
            __half2 h1 = __floats2half2_rn(a4[u][0].z, a4[u][0].w);
            __half2 h2 = __floats2half2_rn(a4[u][1].x, a4[u][1].y);
            __half2 h3 = __floats2half2_rn(a4[u][1].z, a4[u][1].w);
            *(uint4*)&S.A[buf][t * ASTR + g8 * 8] = make_uint4(
                *(uint32_t*)&h0, *(uint32_t*)&h1,
                *(uint32_t*)&h2, *(uint32_t*)&h3);
        }
    };
    auto stageB = [&](int c) {
        const uint4* sp = (c < NCHUNK) ? (g_B4 + c * 1024) : g_Wl4;
        const int nb = c & 1;
#pragma unroll
        for (int u = 0; u < 4; u++) {
            int i = tid + u * 256;
            uint32_t off = (uint32_t)(((i >> 3) * ASTR + (i & 7) * 8) * 2);
            CP_ASYNC16(uB[nb] + off, sp + i);
        }
        CP_COMMIT();
    };
    auto mmaStep = [&](float acc[4][4][4], int k0, uint32_t uAh, uint32_t uBh) {
        uint32_t bf[8];
        uint32_t ab = uBh + (uint32_t)((bRow * ASTR + k0 + bColX) * 2);
        ldsm4(bf,     ab);
        ldsm4(bf + 4, ab + 16 * ASTR * 2);
#pragma unroll
        for (int mi = 0; mi < 4; mi++) {
            uint32_t aoff = (uint32_t)(((aRow + mi * 16) * ASTR + k0 + aColX) * 2);
            uint32_t af[4];
            ldsm4(af, uAh + aoff);
#pragma unroll
            for (int ni = 0; ni < 4; ni++)
                mma16816(acc[mi][ni], af, &bf[ni * 2]);
        }
    };
    auto locFill = [&]() {
        for (int idx = tid; idx < TILE_T * NF; idx += 256) {
            int t = idx >> 5, f = idx & 31;
            float v = S.cb[f];
            const float* wf = &S.ws[f * 2 * NKW];
#pragma unroll
            for (int cc = 0; cc < 2; cc++)
#pragma unroll
                for (int k = 0; k < NKW; k++)
                    v = fmaf(S.al[cc][t + k], wf[cc * NKW + k], v);
            __half h = __float2half_rn(v);
            S.A[0][t * ASTR + f] = ((__half_raw)h).x;
        }
    };

    // ======================= persistent tile loop =======================
    while (true) {
        if (tid == 0) S.ticket = atomicAdd(&g_ticket, 1u);
        __syncthreads();                 // publish ticket; fence prev tile
        const unsigned tile = S.ticket;
        if (tile >= NTILES) break;
        const int b  = (int)(tile >> 5);
        const int tt = (int)(tile & 31);
        const int t0 = tt * TILE_T;

        for (int i = tid; i < 2 * (TILE_T + NKW - 1); i += 256) {
            int c = i / (TILE_T + NKW - 1);
            int p = i % (TILE_T + NKW - 1);
            int t = t0 - NPAD + p;
            S.al[c][p] = (t >= 0 && t < NT)
                       ? alignments[((size_t)b * NT + t) * 2 + c] : 0.f;
        }
        if (tid < NAD) {
            S.pqc[tid] = g_pq[b * NAD + tid] + bm[tid] + bl[tid];
            S.vw[tid]  = v_w[tid];
        }
        memb = memory + ((size_t)b * NT + t0) * NMD;

        float acc[4][4][4];
#pragma unroll
        for (int mi = 0; mi < 4; mi++)
#pragma unroll
            for (int ni = 0; ni < 4; ni++)
#pragma unroll
                for (int j = 0; j < 4; j++) acc[mi][ni][j] = 0.f;

        // Prologue: fully stage chunk 0; prefetch half0 of chunk 1
        stageB(0);
        loadA_half(0, 0);
        convertA_half(0, 0);
        loadA_half(0, 1);
        convertA_half(0, 1);
        loadA_half(1, 0);

        for (int c = 0; c <= NCHUNK; c++) {
            const int nc = c + 1;
            CP_WAIT0();
            __syncthreads();   // publish B(c)+A(c); fence MMA(c-1) reads
            const uint32_t uAh = uA[c & 1];
            const uint32_t uBh = uB[c & 1];

            mmaStep(acc, 0, uAh, uBh);
            if (nc <= NCHUNK) {
                stageB(nc);
                if (nc < NCHUNK) {
                    convertA_half(nc & 1, 0);
                    loadA_half(nc, 1);
                } else {
                    locFill();
                }
            }
            mmaStep(acc, 16, uAh, uBh);
            mmaStep(acc, 32, uAh, uBh);
            if (nc < NCHUNK) {
                convertA_half(nc & 1, 1);
                if (nc + 1 < NCHUNK) loadA_half(nc + 1, 0);
            }
            mmaStep(acc, 48, uAh, uBh);
        }

        // Epilogue: tanh + v-dot, lane-group reduce, 2-stage warp reduce
        float s0[4], s1[4];
#pragma unroll
        for (int mi = 0; mi < 4; mi++) {
            float p0 = 0.f, p1 = 0.f;
#pragma unroll
            for (int ni = 0; ni < 4; ni++) {
#pragma unroll
                for (int j = 0; j < 2; j++) {
                    int cdx = wn * 32 + ni * 8 + tg * 2 + j;
                    p0 = fmaf(S.vw[cdx], tanh_fast(acc[mi][ni][j]     + S.pqc[cdx]), p0);
                    p1 = fmaf(S.vw[cdx], tanh_fast(acc[mi][ni][2 + j] + S.pqc[cdx]), p1);
                }
            }
            p0 += __shfl_xor_sync(0xffffffffu, p0, 1);
            p0 += __shfl_xor_sync(0xffffffffu, p0, 2);
            p1 += __shfl_xor_sync(0xffffffffu, p1, 1);
            p1 += __shfl_xor_sync(0xffffffffu, p1, 2);
            s0[mi] = p0;
            s1[mi] = p1;
        }
        __syncthreads();
        if (wn < 2 && tg == 0) {
#pragma unroll
            for (int mi = 0; mi < 4; mi++) {
                int r = wm * 64 + mi * 16 + g;
                S.part[wn][r]     = s0[mi];
                S.part[wn][r + 8] = s1[mi];
            }
        }
        __syncthreads();
        if (wn >= 2 && tg == 0) {
#pragma unroll
            for (int mi = 0; mi < 4; mi++) {
                int r = wm * 64 + mi * 16 + g;
                S.part[wn - 2][r]     += s0[mi];
                S.part[wn - 2][r + 8] += s1[mi];
            }
        }
        __syncthreads();

        float sc = 0.f;
        if (tid < TILE_T) {
            sc = S.part[0][tid] + S.part[1][tid] + vb;
            if (mask[(size_t)b * NT + t0 + tid]) sc = -CUDART_INF_F;
            g_score[(size_t)b * NT + t0 + tid] = sc;
            S.wexp[tid] = sc;    // temporarily the score
        }
        __syncthreads();

        // ---- split-softmax context partial ----
        // 1) block max over the 128 scores (warps 0..3 hold them)
        if (tid < TILE_T) {
            float m = sc;
            m = fmaxf(m, __shfl_xor_sync(0xffffffffu, m, 16));
            m = fmaxf(m, __shfl_xor_sync(0xffffffffu, m, 8));
            m = fmaxf(m, __shfl_xor_sync(0xffffffffu, m, 4));
            m = fmaxf(m, __shfl_xor_sync(0xffffffffu, m, 2));
            m = fmaxf(m, __shfl_xor_sync(0xffffffffu, m, 1));
            if (lane == 0) S.redm[wid] = m;
        }
        __syncthreads();
        const float mloc = fmaxf(fmaxf(S.redm[0], S.redm[1]),
                                 fmaxf(S.redm[2], S.redm[3]));
        // 2) weights + local Z
        if (tid < TILE_T) {
            float w = __expf(sc - mloc);
            S.wexp[tid] = w;
            w += __shfl_xor_sync(0xffffffffu, w, 16);
            w += __shfl_xor_sync(0xffffffffu, w, 8);
            w += __shfl_xor_sync(0xffffffffu, w, 4);
            w += __shfl_xor_sync(0xffffffffu, w, 2);
            w += __shfl_xor_sync(0xffffffffu, w, 1);
            if (lane == 0) S.redz[wid] = w;
        }
        __syncthreads();
        if (tid == 0) {
            g_pm[tile] = mloc;
            g_pz[tile] = S.redz[0] + S.redz[1] + S.redz[2] + S.redz[3];
        }
        // 3) ctx_i GEMV: 256 threads x float2 columns, rows re-read (L2-hot)
        {
            const float2* mb2 = (const float2*)memb;   // row stride 256 f2
            float2 cacc = make_float2(0.f, 0.f);
#pragma unroll 4
            for (int t = 0; t < TILE_T; t++) {
                float w = S.wexp[t];
                float2 v = mb2[(size_t)t * 256 + tid];
                cacc.x = fmaf(w, v.x, cacc.x);
                cacc.y = fmaf(w, v.y, cacc.y);
            }
            ((float2*)g_pctx)[(size_t)tile * 256 + tid] = cacc;
        }
        // loop-top __syncthreads() fences wexp/part reuse for next tile
    }
}

// ---------------------------------------------------------------------------
// Kernel 3: row softmax over T -> alignment (float4, 1024 threads)
// ---------------------------------------------------------------------------
__global__ void softmax_kernel(float* __restrict__ align_out) {
    int b = blockIdx.x;
    int tid = threadIdx.x;
    __shared__ float red[1024];

    const float4* row = (const float4*)&g_score[(size_t)b * NT];
    float4 v = row[tid];
    float m = fmaxf(fmaxf(v.x, v.y), fmaxf(v.z, v.w));
    red[tid] = m;
    __syncthreads();
    for (int s = 512; s > 0; s >>= 1) {
        if (tid < s) red[tid] = fmaxf(red[tid], red[tid + s]);
        __syncthreads();
    }
    m = red[0];
    __syncthreads();

    float4 e;
    e.x = expf(v.x - m);
    e.y = expf(v.y - m);
    e.z = expf(v.z - m);
    e.w = expf(v.w - m);
    red[tid] = e.x + e.y + e.z + e.w;
    __syncthreads();
    for (int s = 512; s > 0; s >>= 1) {
        if (tid < s) red[tid] += red[tid + s];
        __syncthreads();
    }
    float inv = 1.0f / red[0];
    e.x *= inv; e.y *= inv; e.z *= inv; e.w *= inv;
    ((float4*)&align_out[(size_t)b * NT])[tid] = e;
}

// ---------------------------------------------------------------------------
// Kernel 4: context merge (log-sum-exp combine of 32 tile partials per batch)
// ---------------------------------------------------------------------------
__global__ void merge_kernel(float* __restrict__ ctx) {
    int b = blockIdx.x;
    int tid = threadIdx.x;       // 0..511 (one per m)
    __shared__ float sm[TPB], ss[TPB];

    if (tid < TPB) sm[tid] = g_pm[b * TPB + tid];
    __syncthreads();
    float m = -CUDART_INF_F;
#pragma unroll
    for (int i = 0; i < TPB; i++) m = fmaxf(m, sm[i]);
    if (tid < TPB) ss[tid] = __expf(sm[tid] - m);
    __syncthreads();

    float Z = 0.f;
#pragma unroll
    for (int i = 0; i < TPB; i++) Z += ss[i] * g_pz[b * TPB + i];

    float acc = 0.f;
#pragma unroll 4
    for (int i = 0; i < TPB; i++)
        acc = fmaf(ss[i], g_pctx[(size_t)(b * TPB + i) * NMD + tid], acc);
    ctx[b * NMD + tid] = acc / Z;
}

// ---------------------------------------------------------------------------
// kernel_launch
// ---------------------------------------------------------------------------
extern "C" void kernel_launch(void* const* d_in, const int* in_sizes, int n_in,
                              void* d_out, int out_size) {
    const float* query      = (const float*)d_in[0];
    const float* memory     = (const float*)d_in[1];
    const float* alignments = (const float*)d_in[2];
    const unsigned char* mask = (const unsigned char*)d_in[3];
    const float* Wq     = (const float*)d_in[4];
    const float* bq     = (const float*)d_in[5];
    const float* Wm     = (const float*)d_in[6];
    const float* bm     = (const float*)d_in[7];
    const float* conv_w = (const float*)d_in[8];
    const float* conv_b = (const float*)d_in[9];
    const float* Wl     = (const float*)d_in[10];
    const float* bl     = (const float*)d_in[11];
    const float* v_w    = (const float*)d_in[12];
    const float* v_b    = (const float*)d_in[13];

    float* out       = (float*)d_out;
    float* out_ctx   = out;                // [NB, NMD]
    float* out_align = out + NB * NMD;     // [NB, NT]

    static int nblocks = 0;
    if (!nblocks) {
        cudaFuncSetAttribute(score_kernel,
                             cudaFuncAttributeMaxDynamicSharedMemorySize,
                             (int)sizeof(ScoreSmem));
        int sm = 148;
        cudaDeviceGetAttribute(&sm, cudaDevAttrMultiProcessorCount, 0);
        nblocks = 2 * sm;
    }

    prep_kernel<<<(NMD * NAD + TILE_T * KCH + 255) / 256, 256>>>(Wm, Wl);
    pq_kernel<<<NB, 256>>>(query, Wq, bq);
    score_kernel<<<nblocks, 256, sizeof(ScoreSmem)>>>(
        memory, alignments, mask, bm, conv_w, conv_b, bl, v_w, v_b);
    softmax_kernel<<<NB, 1024>>>(out_align);
    merge_kernel<<<NB, NMD>>>(out_ctx);
}

// round 17
// speedup vs baseline: 1.0288x; 1.0288x over previous
#include <cuda_runtime.h>
#include <cuda_fp16.h>
#include <math.h>
#include <math_constants.h>
#include <stdint.h>

// Problem constants
#define NB   32
#define NT   4096
#define NQD  1024
#define NMD  512
#define NAD  128
#define NF   32
#define NKW  31
#define NPAD 15

// Score-kernel tiling
#define TILE_T  128
#define KCH     64          // K per chunk; loc chunk (chunk 8) uses cols 0..31
#define NCHUNK  8
#define ASTR    72          // padded row stride in elems (144 B, 16B-multiple)
#define NTILES  (NB * (NT / TILE_T))   // 1024 work items

// ---------------------------------------------------------------------------
// Device scratch (no allocation allowed). uint4-typed => 16B alignment.
// ---------------------------------------------------------------------------
__device__ alignas(16) float g_pq[NB * NAD];
__device__ alignas(16) float g_score[NB * NT];
__device__ unsigned g_ticket;
// fp16 B operands: [chunk][a(128)][k(64)] packed as uint4 (8 halfs)
__device__ uint4 g_B4[NCHUNK * TILE_T * KCH / 8];
__device__ uint4 g_Wl4[TILE_T * KCH / 8];   // cols 32..63 zero

// ---------------------------------------------------------------------------
// Shared memory: fp16 A and B tiles, double-buffered, KCH=64.
// ---------------------------------------------------------------------------
struct ScoreSmem {
    alignas(16) unsigned short A[2][TILE_T * ASTR];
    alignas(16) unsigned short B[2][TILE_T * ASTR];
    float pqc[NAD];
    float vw[NAD];
    float al[2][TILE_T + NKW - 1];
    float ws[NF * 2 * NKW];     // 1984 floats
    float cb[NF];
    float part[2][TILE_T];
    unsigned ticket;
};
static_assert(sizeof(ScoreSmem) <= 100 * 1024, "smem overflow");

// ---------------------------------------------------------------------------
// Helpers
// ---------------------------------------------------------------------------
__device__ __forceinline__ uint32_t smem_u32(const void* p) {
    uint32_t r;
    asm("{ .reg .u64 t; cvta.to.shared.u64 t, %1; cvt.u32.u64 %0, t; }"
        : "=r"(r) : "l"(p));
    return r;
}

__device__ __forceinline__ void ldsm4(uint32_t* r, uint32_t addr) {
    asm volatile("ldmatrix.sync.aligned.m8n8.x4.shared.b16 {%0,%1,%2,%3}, [%4];"
                 : "=r"(r[0]), "=r"(r[1]), "=r"(r[2]), "=r"(r[3]) : "r"(addr));
}

__device__ __forceinline__ void mma16816(float* c, const uint32_t* a,
                                         const uint32_t* b) {
    asm volatile(
        "mma.sync.aligned.m16n8k16.row.col.f32.f16.f16.f32 "
        "{%0,%1,%2,%3}, {%4,%5,%6,%7}, {%8,%9}, {%0,%1,%2,%3};"
        : "+f"(c[0]), "+f"(c[1]), "+f"(c[2]), "+f"(c[3])
        : "r"(a[0]), "r"(a[1]), "r"(a[2]), "r"(a[3]), "r"(b[0]), "r"(b[1]));
}

#define CP_ASYNC16(dst_u32, src_ptr) \
    asm volatile("cp.async.cg.shared.global [%0], [%1], 16;" \
                 :: "r"(dst_u32), "l"(src_ptr))
#define CP_COMMIT() asm volatile("cp.async.commit_group;")
#define CP_WAIT0()  asm volatile("cp.async.wait_group 0;")

__device__ __forceinline__ float tanh_fast(float x) {
    x = fminf(fmaxf(x, -20.f), 20.f);
    float e = __expf(-2.f * x);
    return __fdividef(1.f - e, 1.f + e);
}

// ---------------------------------------------------------------------------
// Prep: convert Wm / Wl to fp16, [chunk][a][k64] layout; Wl cols>=32 zeroed
// ---------------------------------------------------------------------------
__global__ void prep_kernel(const float* __restrict__ Wm,
                            const float* __restrict__ Wl) {
    int idx = blockIdx.x * blockDim.x + threadIdx.x;
    unsigned short* bp = (unsigned short*)g_B4;
    unsigned short* wp = (unsigned short*)g_Wl4;
    if (idx < NMD * NAD) {
        int k = idx >> 7, a = idx & 127;
        int c = k >> 6, kk = k & 63;
        __half h = __float2half_rn(Wm[k * NAD + a]);
        bp[c * (TILE_T * KCH) + a * KCH + kk] = ((__half_raw)h).x;
    } else if (idx < NMD * NAD + TILE_T * KCH) {
        int r = idx - NMD * NAD;
        int a = r >> 6, kk = r & 63;
        float v = (kk < NF) ? Wl[kk * NAD + a] : 0.0f;
        __half h = __float2half_rn(v);
        wp[a * KCH + kk] = ((__half_raw)h).x;
    }
}

// ---------------------------------------------------------------------------
// Kernel 1: processed query + ticket reset + ctx zeroing (folded)
// ---------------------------------------------------------------------------
__global__ void pq_kernel(const float* __restrict__ query,
                          const float* __restrict__ Wq,
                          const float* __restrict__ bq,
                          float* __restrict__ ctx) {
    __shared__ float qs[NQD];
    __shared__ float partial[256];
    int b = blockIdx.x;
    int tid = threadIdx.x;
    if (b == 0 && tid == 0) g_ticket = 0;
    ctx[b * NMD + tid]       = 0.f;
    ctx[b * NMD + 256 + tid] = 0.f;
    for (int i = tid; i < NQD; i += 256)
        qs[i] = query[b * NQD + i];
    __syncthreads();
    int a = tid & 127;
    int h = tid >> 7;
    float acc = 0.f;
    int q0 = h * (NQD / 2);
#pragma unroll 8
    for (int q = 0; q < NQD / 2; q++)
        acc = fmaf(qs[q0 + q], Wq[(q0 + q) * NAD + a], acc);
    partial[tid] = acc;
    __syncthreads();
    if (tid < 128)
        g_pq[b * NAD + a] = bq[a] + partial[tid] + partial[tid + 128];
}

// ---------------------------------------------------------------------------
// Kernel 2: PERSISTENT fused score kernel, fp16 GEMM, KCH=64 (9 chunks).
// (Reverted to the proven R13 structure.)
// ---------------------------------------------------------------------------
__global__ __launch_bounds__(256, 2)
void score_kernel(const float* __restrict__ memory,
                  const float* __restrict__ alignments,
                  const unsigned char* __restrict__ mask,
                  const float* __restrict__ bm,
                  const float* __restrict__ conv_w,
                  const float* __restrict__ conv_b,
                  const float* __restrict__ bl,
                  const float* __restrict__ v_w,
                  const float* __restrict__ v_b) {
    extern __shared__ char smem_raw[];
    ScoreSmem& S = *reinterpret_cast<ScoreSmem*>(smem_raw);

    const int tid  = threadIdx.x;
    const int lane = tid & 31;
    const int wid  = tid >> 5;
    const int wm   = wid >> 2;
    const int wn   = wid & 3;
    const int g    = lane >> 2;
    const int tg   = lane & 3;

    for (int i = tid; i < NF * 2 * NKW; i += 256) S.ws[i] = conv_w[i];
    if (tid < NF) S.cb[tid] = conv_b[tid];
    const float vb = *v_b;

    const uint32_t uA[2] = {smem_u32(S.A[0]), smem_u32(S.A[1])};
    const uint32_t uB[2] = {smem_u32(S.B[0]), smem_u32(S.B[1])};

    // ldmatrix per-lane addressing
    const int aRow  = wm * 64 + (lane & 15);
    const int aColX = (lane >> 4) * 8;
    const int bRow  = wn * 32 + ((lane >> 4) << 3) + (lane & 7);
    const int bColX = ((lane >> 3) & 1) * 8;

    float4 a4[2][2];     // one half-chunk (16 floats)
    const float* memb = memory;

    auto loadA_half = [&](int c, int h) {
#pragma unroll
        for (int u = 0; u < 2; u++) {
            int unit = tid + (2 * h + u) * 256;
            int t = unit >> 3, g8 = unit & 7;
            const float* src = memb + (size_t)t * NMD + c * KCH + g8 * 8;
            a4[u][0] = *(const float4*)src;
            a4[u][1] = *(const float4*)(src + 4);
        }
    };
    auto convertA_half = [&](int buf, int h) {
#pragma unroll
        for (int u = 0; u < 2; u++) {
            int unit = tid + (2 * h + u) * 256;
            int t = unit >> 3, g8 = unit & 7;
            __half2 h0 = __floats2half2_rn(a4[u][0].x, a4[u][0].y);
            __half2 h1 = __floats2half2_rn(a4[u][0].z, a4[u][0].w);
            __half2 h2 = __floats2half2_rn(a4[u][1].x, a4[u][1].y);
            __half2 h3 = __floats2half2_rn(a4[u][1].z, a4[u][1].w);
            *(uint4*)&S.A[buf][t * ASTR + g8 * 8] = make_uint4(
                *(uint32_t*)&h0, *(uint32_t*)&h1,
                *(uint32_t*)&h2, *(uint32_t*)&h3);
        }
    };
    auto stageB = [&](int c) {
        const uint4* sp = (c < NCHUNK) ? (g_B4 + c * 1024) : g_Wl4;
        const int nb = c & 1;
#pragma unroll
        for (int u = 0; u < 4; u++) {
            int i = tid + u * 256;
            uint32_t off = (uint32_t)(((i >> 3) * ASTR + (i & 7) * 8) * 2);
            CP_ASYNC16(uB[nb] + off, sp + i);
        }
        CP_COMMIT();
    };
    auto mmaStep = [&](float acc[4][4][4], int k0, uint32_t uAh, uint32_t uBh) {
        uint32_t bf[8];
        uint32_t ab = uBh + (uint32_t)((bRow * ASTR + k0 + bColX) * 2);
        ldsm4(bf,     ab);
        ldsm4(bf + 4, ab + 16 * ASTR * 2);
#pragma unroll
        for (int mi = 0; mi < 4; mi++) {
            uint32_t aoff = (uint32_t)(((aRow + mi * 16) * ASTR + k0 + aColX) * 2);
            uint32_t af[4];
            ldsm4(af, uAh + aoff);
#pragma unroll
            for (int ni = 0; ni < 4; ni++)
                mma16816(acc[mi][ni], af, &bf[ni * 2]);
        }
    };
    auto locFill = [&]() {
        for (int idx = tid; idx < TILE_T * NF; idx += 256) {
            int t = idx >> 5, f = idx & 31;
            float v = S.cb[f];
            const float* wf = &S.ws[f * 2 * NKW];
#pragma unroll
            for (int cc = 0; cc < 2; cc++)
#pragma unroll
                for (int k = 0; k < NKW; k++)
                    v = fmaf(S.al[cc][t + k], wf[cc * NKW + k], v);
            __half h = __float2half_rn(v);
            S.A[0][t * ASTR + f] = ((__half_raw)h).x;
        }
    };

    // ======================= persistent tile loop =======================
    while (true) {
        if (tid == 0) S.ticket = atomicAdd(&g_ticket, 1u);
        __syncthreads();                 // publish ticket; fence prev tile
        const unsigned tile = S.ticket;
        if (tile >= NTILES) break;
        const int b  = (int)(tile >> 5);
        const int t0 = (int)(tile & 31) * TILE_T;

        for (int i = tid; i < 2 * (TILE_T + NKW - 1); i += 256) {
            int c = i / (TILE_T + NKW - 1);
            int p = i % (TILE_T + NKW - 1);
            int t = t0 - NPAD + p;
            S.al[c][p] = (t >= 0 && t < NT)
                       ? alignments[((size_t)b * NT + t) * 2 + c] : 0.f;
        }
        if (tid < NAD) {
            S.pqc[tid] = g_pq[b * NAD + tid] + bm[tid] + bl[tid];
            S.vw[tid]  = v_w[tid];
        }
        memb = memory + ((size_t)b * NT + t0) * NMD;

        float acc[4][4][4];
#pragma unroll
        for (int mi = 0; mi < 4; mi++)
#pragma unroll
            for (int ni = 0; ni < 4; ni++)
#pragma unroll
                for (int j = 0; j < 4; j++) acc[mi][ni][j] = 0.f;

        // Prologue: fully stage chunk 0; prefetch half0 of chunk 1
        stageB(0);
        loadA_half(0, 0);
        convertA_half(0, 0);
        loadA_half(0, 1);
        convertA_half(0, 1);
        loadA_half(1, 0);

        // --- 9 chunks (chunk 8 == fused location conv) ---
        for (int c = 0; c <= NCHUNK; c++) {
            const int nc = c + 1;
            CP_WAIT0();
            __syncthreads();   // publish B(c)+A(c); fence MMA(c-1) reads
            const uint32_t uAh = uA[c & 1];
            const uint32_t uBh = uB[c & 1];

            mmaStep(acc, 0, uAh, uBh);
            if (nc <= NCHUNK) {
                stageB(nc);
                if (nc < NCHUNK) {
                    convertA_half(nc & 1, 0);   // from a4 (prefetched)
                    loadA_half(nc, 1);
                } else {
                    locFill();                  // chunk 8 A (buffer 0)
                }
            }
            mmaStep(acc, 16, uAh, uBh);
            mmaStep(acc, 32, uAh, uBh);
            if (nc < NCHUNK) {
                convertA_half(nc & 1, 1);
                if (nc + 1 < NCHUNK) loadA_half(nc + 1, 0);
            }
            mmaStep(acc, 48, uAh, uBh);
        }

        // Epilogue: tanh + v-dot, lane-group reduce, 2-stage warp reduce
        float s0[4], s1[4];
#pragma unroll
        for (int mi = 0; mi < 4; mi++) {
            float p0 = 0.f, p1 = 0.f;
#pragma unroll
            for (int ni = 0; ni < 4; ni++) {
#pragma unroll
                for (int j = 0; j < 2; j++) {
                    int cdx = wn * 32 + ni * 8 + tg * 2 + j;
                    p0 = fmaf(S.vw[cdx], tanh_fast(acc[mi][ni][j]     + S.pqc[cdx]), p0);
                    p1 = fmaf(S.vw[cdx], tanh_fast(acc[mi][ni][2 + j] + S.pqc[cdx]), p1);
                }
            }
            p0 += __shfl_xor_sync(0xffffffffu, p0, 1);
            p0 += __shfl_xor_sync(0xffffffffu, p0, 2);
            p1 += __shfl_xor_sync(0xffffffffu, p1, 1);
            p1 += __shfl_xor_sync(0xffffffffu, p1, 2);
            s0[mi] = p0;
            s1[mi] = p1;
        }
        __syncthreads();
        if (wn < 2 && tg == 0) {
#pragma unroll
            for (int mi = 0; mi < 4; mi++) {
                int r = wm * 64 + mi * 16 + g;
                S.part[wn][r]     = s0[mi];
                S.part[wn][r + 8] = s1[mi];
            }
        }
        __syncthreads();
        if (wn >= 2 && tg == 0) {
#pragma unroll
            for (int mi = 0; mi < 4; mi++) {
                int r = wm * 64 + mi * 16 + g;
                S.part[wn - 2][r]     += s0[mi];
                S.part[wn - 2][r + 8] += s1[mi];
            }
        }
        __syncthreads();

        if (tid < TILE_T) {
            float sc = S.part[0][tid] + S.part[1][tid] + vb;
            if (mask[(size_t)b * NT + t0 + tid]) sc = -CUDART_INF_F;
            g_score[(size_t)b * NT + t0 + tid] = sc;
        }
    }
}

// ---------------------------------------------------------------------------
// Kernel 3: row softmax over T -> alignment (float4, 1024 threads)
// ---------------------------------------------------------------------------
__global__ void softmax_kernel(float* __restrict__ align_out) {
    int b = blockIdx.x;
    int tid = threadIdx.x;
    __shared__ float red[1024];

    const float4* row = (const float4*)&g_score[(size_t)b * NT];
    float4 v = row[tid];
    float m = fmaxf(fmaxf(v.x, v.y), fmaxf(v.z, v.w));
    red[tid] = m;
    __syncthreads();
    for (int s = 512; s > 0; s >>= 1) {
        if (tid < s) red[tid] = fmaxf(red[tid], red[tid + s]);
        __syncthreads();
    }
    m = red[0];
    __syncthreads();

    float4 e;
    e.x = expf(v.x - m);
    e.y = expf(v.y - m);
    e.z = expf(v.z - m);
    e.w = expf(v.w - m);
    red[tid] = e.x + e.y + e.z + e.w;
    __syncthreads();
    for (int s = 512; s > 0; s >>= 1) {
        if (tid < s) red[tid] += red[tid + s];
        __syncthreads();
    }
    float inv = 1.0f / red[0];
    e.x *= inv; e.y *= inv; e.z *= inv; e.w *= inv;
    ((float4*)&align_out[(size_t)b * NT])[tid] = e;
}

// ---------------------------------------------------------------------------
// Kernel 4: context — TCH=128 for higher block-level parallelism (1024 blocks)
// ---------------------------------------------------------------------------
#define TCH 128
__global__ __launch_bounds__(256)
void context_kernel(const float* __restrict__ memory,
                    const float* __restrict__ align,
                    float* __restrict__ ctx) {
    int b  = blockIdx.y;
    int tc = blockIdx.x;
    int m4 = threadIdx.x & 127;   // float4 column group (512/4 = 128)
    int th = threadIdx.x >> 7;    // 0..1 t-half (64 rows each)

    __shared__ float al[TCH];
    __shared__ float4 red[128];
    if (threadIdx.x < TCH)
        al[threadIdx.x] = align[(size_t)b * NT + tc * TCH + threadIdx.x];
    __syncthreads();

    const float4* mb = (const float4*)(memory +
        (size_t)b * NT * NMD + (size_t)(tc * TCH + th * 64) * NMD);
    float4 acc = make_float4(0.f, 0.f, 0.f, 0.f);
    const float* alh = &al[th * 64];
#pragma unroll 8
    for (int t = 0; t < 64; t++) {
        float a = alh[t];
        float4 v = mb[(size_t)t * 128 + m4];
        acc.x = fmaf(a, v.x, acc.x);
        acc.y = fmaf(a, v.y, acc.y);
        acc.z = fmaf(a, v.z, acc.z);
        acc.w = fmaf(a, v.w, acc.w);
    }
    if (th == 1) red[m4] = acc;
    __syncthreads();
    if (th == 0) {
        float4 o = red[m4];
        acc.x += o.x; acc.y += o.y; acc.z += o.z; acc.w += o.w;
        float* dst = &ctx[b * NMD + m4 * 4];
        atomicAdd(dst + 0, acc.x);
        atomicAdd(dst + 1, acc.y);
        atomicAdd(dst + 2, acc.z);
        atomicAdd(dst + 3, acc.w);
    }
}

// ---------------------------------------------------------------------------
// kernel_launch
// ---------------------------------------------------------------------------
extern "C" void kernel_launch(void* const* d_in, const int* in_sizes, int n_in,
                              void* d_out, int out_size) {
    const float* query      = (const float*)d_in[0];
    const float* memory     = (const float*)d_in[1];
    const float* alignments = (const float*)d_in[2];
    const unsigned char* mask = (const unsigned char*)d_in[3];
    const float* Wq     = (const float*)d_in[4];
    const float* bq     = (const float*)d_in[5];
    const float* Wm     = (const float*)d_in[6];
    const float* bm     = (const float*)d_in[7];
    const float* conv_w = (const float*)d_in[8];
    const float* conv_b = (const float*)d_in[9];
    const float* Wl     = (const float*)d_in[10];
    const float* bl     = (const float*)d_in[11];
    const float* v_w    = (const float*)d_in[12];
    const float* v_b    = (const float*)d_in[13];

    float* out       = (float*)d_out;
    float* out_ctx   = out;                // [NB, NMD]
    float* out_align = out + NB * NMD;     // [NB, NT]

    static int nblocks = 0;
    if (!nblocks) {
        cudaFuncSetAttribute(score_kernel,
                             cudaFuncAttributeMaxDynamicSharedMemorySize,
                             (int)sizeof(ScoreSmem));
        int sm = 148;
        cudaDeviceGetAttribute(&sm, cudaDevAttrMultiProcessorCount, 0);
        nblocks = 2 * sm;
    }

    prep_kernel<<<(NMD * NAD + TILE_T * KCH + 255) / 256, 256>>>(Wm, Wl);
    pq_kernel<<<NB, 256>>>(query, Wq, bq, out_ctx);
    score_kernel<<<nblocks, 256, sizeof(ScoreSmem)>>>(
        memory, alignments, mask, bm, conv_w, conv_b, bl, v_w, v_b);
    softmax_kernel<<<NB, 1024>>>(out_align);
    context_kernel<<<dim3(NT / TCH, NB), 256>>>(memory, out_align, out_ctx);
}